// round 17
// baseline (speedup 1.0000x reference)
#include <cuda_runtime.h>
#include <cuda_bf16.h>
#include <cuda_fp16.h>
#include <cstdint>
#include <math.h>

// ---------------- problem constants ----------------
#define D_MODEL   1024
#define D_INNER   2048
#define D_STATE   64
#define HEADDIM   128
#define NHEADS    16
#define D_CONV    4
#define CONV_DIM  2176
#define D_IN_PROJ 4240
#define BATCH     2
#define SEQLEN    4096
#define NROWS     (BATCH*SEQLEN)  // 8192
#define RMS_EPS   1e-5f

#define LCHUNK    128
#define NCHUNK    (SEQLEN/LCHUNK)   // 32

// ---------------- scratch ----------------
__device__ float g_zx  [(size_t)NROWS * D_IN_PROJ];
__device__ float g_xbc [(size_t)NROWS * CONV_DIM];
__device__ __half g_xbch[(size_t)NROWS * CONV_DIM];
__device__ float g_ldec[(size_t)NROWS * NHEADS];
__device__ float g_y   [(size_t)NROWS * D_INNER];
__device__ float g_st  [(size_t)BATCH * NHEADS * NCHUNK * HEADDIM * D_STATE];
__device__ float g_cum [(size_t)BATCH * NHEADS * NCHUNK * LCHUNK];
__device__ __half g_uh [(size_t)NROWS * D_MODEL];
__device__ __half g_w1h[(size_t)D_IN_PROJ * D_MODEL];
__device__ __half g_w2h[(size_t)D_MODEL * D_INNER];
__device__ __half g_ygh[(size_t)NROWS * D_INNER];

// ================= helpers =================
__device__ __forceinline__ uint32_t smem_to_u32(const void* p) {
    uint32_t a;
    asm("{ .reg .u64 t; cvta.to.shared.u64 t, %1; cvt.u32.u64 %0, t; }"
        : "=r"(a) : "l"(p));
    return a;
}
__device__ __forceinline__ uint32_t packh2(float a, float b) {
    uint32_t r;
    asm("cvt.rn.f16x2.f32 %0, %1, %2;" : "=r"(r) : "f"(b), "f"(a));
    return r;
}
__device__ __forceinline__ float2 h2f2(uint32_t w) {
    __half2 h = *(__half2*)&w;
    return __half22float2(h);
}
__device__ __forceinline__ void mma_fp16(float* d, const uint32_t* a,
                                         const uint32_t* b) {
    asm volatile(
        "mma.sync.aligned.m16n8k16.row.col.f32.f16.f16.f32 "
        "{%0,%1,%2,%3},{%4,%5,%6,%7},{%8,%9},{%0,%1,%2,%3};"
        : "+f"(d[0]), "+f"(d[1]), "+f"(d[2]), "+f"(d[3])
        : "r"(a[0]), "r"(a[1]), "r"(a[2]), "r"(a[3]), "r"(b[0]), "r"(b[1]));
}
__device__ __forceinline__ void ldsm_x4(uint32_t& r0, uint32_t& r1,
                                        uint32_t& r2, uint32_t& r3,
                                        uint32_t addr) {
    asm volatile("ldmatrix.sync.aligned.m8n8.x4.shared.b16 {%0,%1,%2,%3}, [%4];"
                 : "=r"(r0), "=r"(r1), "=r"(r2), "=r"(r3) : "r"(addr));
}
__device__ __forceinline__ void ldsm_x4_t(uint32_t& r0, uint32_t& r1,
                                          uint32_t& r2, uint32_t& r3,
                                          uint32_t addr) {
    asm volatile("ldmatrix.sync.aligned.m8n8.x4.trans.shared.b16 {%0,%1,%2,%3}, [%4];"
                 : "=r"(r0), "=r"(r1), "=r"(r2), "=r"(r3) : "r"(addr));
}
__device__ __forceinline__ float fast_sigmoid(float x) {
    return __fdividef(1.f, 1.f + __expf(-x));
}
// swizzled addressing: 128B rows (64 fp16), col2 = uint32 index 0..31
__device__ __forceinline__ uint32_t a128(uint32_t base, int row, int col2) {
    return base + (uint32_t)(row * 128 + ((((col2 >> 2) ^ row) & 7) * 16) + (col2 & 3) * 4);
}
// swizzled addressing: 256B rows (128 fp16), col2 0..63
__device__ __forceinline__ uint32_t a256(uint32_t base, int row, int col2) {
    int cq = col2 >> 2;
    int ph = (((cq & 7) ^ (row & 7)) | (cq & 8));
    return base + (uint32_t)(row * 256 + ph * 16 + (col2 & 3) * 4);
}

// ================= split kernel: fp32 -> fp16 ==============================
__global__ __launch_bounds__(256) void split_kernel(
    const float* __restrict__ in, __half* __restrict__ out, int n4)
{
    int i = blockIdx.x * 256 + threadIdx.x;
    if (i >= n4) return;
    float4 v = ((const float4*)in)[i];
    ((uint2*)out)[i] = make_uint2(packh2(v.x, v.y), packh2(v.z, v.w));
}

// ================= GEMM (fp16, K=64 chunks, 3-stage cp.async) ==============
#define GB_M 128
#define GB_N 128
#define GB_K 64
#define GB_STAGE 32768
#define GB_SMEM_BYTES (3 * GB_STAGE)   // 98304

__global__ __launch_bounds__(256, 2) void gemm_fp16(
    const __half* __restrict__ A, const __half* __restrict__ B,
    float* __restrict__ C, int M, int N, int K, int ldc)
{
    extern __shared__ char smem[];
    const uint32_t sbase = smem_to_u32(smem);
    const int tid = threadIdx.x;
    const int bm  = blockIdx.y * GB_M;
    const int bn  = blockIdx.x * GB_N;
    const int nch = K / GB_K;

    const int warp = tid >> 5;
    const int lane = tid & 31;
    const int wm = warp >> 2;
    const int wn = warp & 3;
    const int lr = lane >> 2;
    const int lc = lane & 3;

    float acc[4][4][4];
    #pragma unroll
    for (int mt = 0; mt < 4; mt++)
        #pragma unroll
        for (int nt = 0; nt < 4; nt++)
            #pragma unroll
            for (int q = 0; q < 4; q++) acc[mt][nt][q] = 0.f;

    auto load_stage = [&](int buf, int kt) {
        #pragma unroll
        for (int i = 0; i < 8; i++) {
            int idx = tid + i * 256;
            int cq = idx & 7;
            int r  = (idx >> 3) & 127;
            int t  = idx >> 10;
            uint32_t so = sbase + (uint32_t)buf * GB_STAGE + (uint32_t)t * 16384 +
                          (uint32_t)r * 128 + (uint32_t)(((cq ^ r) & 7) * 16);
            const __half* g;
            if (t == 0) g = A + (size_t)(bm + r) * K;
            else {
                int gn = bn + r; if (gn >= N) gn = N - 1;
                g = B + (size_t)gn * K;
            }
            g += kt + cq * 8;
            asm volatile("cp.async.cg.shared.global [%0], [%1], 16;"
                         :: "r"(so), "l"(g));
        }
        asm volatile("cp.async.commit_group;");
    };

    load_stage(0, 0);
    if (nch > 1) load_stage(1, GB_K);

    const int rowA = wm * 64 + ((lane >> 3) & 1) * 8 + (lane & 7);
    const int rowB = wn * 32 + ((lane >> 4) & 1) * 8 + (lane & 7);
    const int cAq  = (lane >> 4) & 1;
    const int cBq  = (lane >> 3) & 1;
    const int rA7  = rowA & 7;
    const int rB7  = rowB & 7;

    for (int c = 0; c < nch; c++) {
        if (c == nch - 1) asm volatile("cp.async.wait_group 0;");
        else              asm volatile("cp.async.wait_group 1;");
        __syncthreads();
        if (c + 2 < nch) load_stage((c + 2) % 3, (c + 2) * GB_K);

        const uint32_t stg = sbase + (uint32_t)(c % 3) * GB_STAGE;
        const uint32_t baseA = stg + (uint32_t)rowA * 128;
        const uint32_t baseB = stg + 16384 + (uint32_t)rowB * 128;

        #pragma unroll
        for (int ks = 0; ks < 4; ks++) {
            const uint32_t cAo = (uint32_t)((((ks * 2 + cAq) ^ rA7) & 7) * 16);
            const uint32_t cBo = (uint32_t)((((ks * 2 + cBq) ^ rB7) & 7) * 16);

            uint32_t bh[4][2];
            #pragma unroll
            for (int ntp = 0; ntp < 2; ntp++) {
                uint32_t r0, r1, r2, r3;
                ldsm_x4(r0, r1, r2, r3, baseB + ntp * 2048 + cBo);
                bh[ntp*2][0] = r0; bh[ntp*2][1] = r1;
                bh[ntp*2+1][0] = r2; bh[ntp*2+1][1] = r3;
            }
            #pragma unroll
            for (int mt = 0; mt < 4; mt++) {
                uint32_t ah[4];
                ldsm_x4(ah[0], ah[1], ah[2], ah[3], baseA + mt * 2048 + cAo);
                #pragma unroll
                for (int nt = 0; nt < 4; nt++)
                    mma_fp16(acc[mt][nt], ah, bh[nt]);
            }
        }
    }

    #pragma unroll
    for (int mt = 0; mt < 4; mt++) {
        int row = bm + wm * 64 + mt * 16 + lr;
        #pragma unroll
        for (int nt = 0; nt < 4; nt++) {
            int col = bn + wn * 32 + nt * 8 + lc * 2;
            if (col + 1 < N) {
                *(float2*)(C + (size_t)row * ldc + col) =
                    make_float2(acc[mt][nt][0], acc[mt][nt][1]);
                *(float2*)(C + (size_t)(row + 8) * ldc + col) =
                    make_float2(acc[mt][nt][2], acc[mt][nt][3]);
            }
        }
    }
}

// ---------------- depthwise causal conv + bias + SiLU (+ fp16 mirror) ------
__global__ __launch_bounds__(256) void conv_kernel(
    const float* __restrict__ zx, const float* __restrict__ cw,
    const float* __restrict__ cb, float* __restrict__ xbc,
    __half* __restrict__ xbch)
{
    int c = blockIdx.x * 256 + threadIdx.x;
    if (c >= CONV_DIM) return;
    int strip = blockIdx.y;
    int b     = blockIdx.z;
    int l0    = strip * 256;

    float w0 = cw[c*4+0], w1 = cw[c*4+1], w2 = cw[c*4+2], w3 = cw[c*4+3];
    float bias = cb[c];

    size_t colbase = (size_t)D_INNER + c;
    size_t rb = (size_t)b * SEQLEN;

    float xm3 = (l0-3 >= 0) ? zx[(rb + l0-3) * D_IN_PROJ + colbase] : 0.f;
    float xm2 = (l0-2 >= 0) ? zx[(rb + l0-2) * D_IN_PROJ + colbase] : 0.f;
    float xm1 = (l0-1 >= 0) ? zx[(rb + l0-1) * D_IN_PROJ + colbase] : 0.f;

    for (int l = l0; l < l0 + 256; l++) {
        float xv = zx[(rb + l) * D_IN_PROJ + colbase];
        float a = bias;
        a = fmaf(w0, xm3, a);
        a = fmaf(w1, xm2, a);
        a = fmaf(w2, xm1, a);
        a = fmaf(w3, xv,  a);
        float sv = a * fast_sigmoid(a);
        xbc [(rb + l) * CONV_DIM + c] = sv;
        xbch[(rb + l) * CONV_DIM + c] = __float2half(sv);
        xm3 = xm2; xm2 = xm1; xm1 = xv;
    }
}

// ---------------- dt -> softplus -> LOG decay ------------------------------
__global__ __launch_bounds__(256) void decay_kernel(
    const float* __restrict__ zx, const float* __restrict__ dt_bias,
    const float* __restrict__ A_log, float* __restrict__ ldec)
{
    int idx = blockIdx.x * 256 + threadIdx.x;
    if (idx >= NROWS * NHEADS) return;
    int r = idx >> 4;
    int h = idx & 15;
    float raw = zx[(size_t)r * D_IN_PROJ + (D_IN_PROJ - NHEADS) + h] + dt_bias[h];
    float sp  = (raw > 20.f) ? raw : log1pf(expf(raw));
    float A   = -expf(A_log[h]);
    ldec[idx] = sp * A;
}

// ================= chunked matmul scan (intra-chunk, fp16, async-fed) ======
#define SM_XT  0u         // 32KB  X[s=128 rows][p=128] fp16, a256 swizzle
#define SM_CB  32768u     // C 16KB @32768, B 16KB @49152; later G 32KB (a256)
#define SM_WB  65536u     // 16KB  WB[64n][128s] (a256)
#define SM_L   81920u     // 512B
#define SM_SMEM 82432u

__global__ __launch_bounds__(256, 2) void scan_matmul_kernel(
    const float* __restrict__ xbc, const __half* __restrict__ xbch,
    const float* __restrict__ ldec,
    const float* __restrict__ Dvec, float* __restrict__ yout,
    float* __restrict__ states, float* __restrict__ cumout)
{
    extern __shared__ char smem[];
    const uint32_t sb = smem_to_u32(smem);
    const int c = blockIdx.x;
    const int h = blockIdx.y;
    const int b = blockIdx.z;
    const int t = threadIdx.x;
    const int warp = t >> 5;
    const int lane = t & 31;
    const int lr = lane >> 2;
    const int lc = lane & 3;

    const size_t base = (size_t)b * SEQLEN + (size_t)c * LCHUNK;
    const int xcol = h * HEADDIM;
    const size_t cumbase = (size_t)(((b * NHEADS + h) * NCHUNK) + c) * LCHUNK;

    float* Lsm = (float*)(smem + SM_L);

    // ---- async stage: X rows (256B), C rows (+64, 128B), B rows (+0, 128B)
    {
        #pragma unroll
        for (int i = 0; i < 8; i++) {
            int idx = t + i * 256;          // 0..2047: X chunks
            int r = idx >> 4, cq = idx & 15;
            const __half* src = xbch + (base + r) * CONV_DIM + xcol + cq * 8;
            uint32_t dst = sb + SM_XT + (uint32_t)(r * 256 +
                           ((((cq & 7) ^ (r & 7)) | (cq & 8)) * 16));
            asm volatile("cp.async.cg.shared.global [%0], [%1], 16;"
                         :: "r"(dst), "l"(src));
        }
        #pragma unroll
        for (int i = 0; i < 8; i++) {
            int idx = t + i * 256;          // 0..2047: C then B
            int cq = idx & 7;
            int r  = (idx >> 3) & 127;
            int which = idx >> 10;          // 0: C (+64), 1: B (+0)
            const __half* src = xbch + (base + r) * CONV_DIM + D_INNER +
                                (which ? 0 : 64) + cq * 8;
            uint32_t dst = sb + SM_CB + (uint32_t)which * 16384 +
                           (uint32_t)(r * 128 + (((cq ^ r) & 7) * 16));
            asm volatile("cp.async.cg.shared.global [%0], [%1], 16;"
                         :: "r"(dst), "l"(src));
        }
        asm volatile("cp.async.commit_group;");
    }

    // ---- log-decay prefix (warp 0) + cum output (overlaps async copies) ----
    if (warp == 0) {
        float v0 = ldec[(base + lane * 4 + 0) * NHEADS + h];
        float v1 = ldec[(base + lane * 4 + 1) * NHEADS + h];
        float v2 = ldec[(base + lane * 4 + 2) * NHEADS + h];
        float v3 = ldec[(base + lane * 4 + 3) * NHEADS + h];
        float p0 = v0, p1 = p0 + v1, p2 = p1 + v2, p3 = p2 + v3;
        float inc = p3;
        #pragma unroll
        for (int o = 1; o < 32; o <<= 1) {
            float n = __shfl_up_sync(0xffffffffu, inc, o);
            if (lane >= o) inc += n;
        }
        float excl = inc - p3;
        Lsm[lane*4+0] = excl + p0;
        Lsm[lane*4+1] = excl + p1;
        Lsm[lane*4+2] = excl + p2;
        Lsm[lane*4+3] = excl + p3;
        cumout[cumbase + lane*4+0] = __expf(excl + p0);
        cumout[cumbase + lane*4+1] = __expf(excl + p1);
        cumout[cumbase + lane*4+2] = __expf(excl + p2);
        cumout[cumbase + lane*4+3] = __expf(excl + p3);
    }

    asm volatile("cp.async.wait_group 0;");
    __syncthreads();

    // ---- step 1: G = C·B^T  (M=128 l, N=128 s, K=64 n) ----
    const int wm = warp >> 2, wn = warp & 3;
    const int rowA = wm * 64 + ((lane >> 3) & 1) * 8 + (lane & 7);
    const int rowB = wn * 32 + ((lane >> 4) & 1) * 8 + (lane & 7);
    const int cAq = (lane >> 4) & 1;
    const int cBq = (lane >> 3) & 1;
    const int rA7 = rowA & 7, rB7 = rowB & 7;

    float acc1[4][4][4];
    #pragma unroll
    for (int mt = 0; mt < 4; mt++)
        #pragma unroll
        for (int nt = 0; nt < 4; nt++)
            #pragma unroll
            for (int q = 0; q < 4; q++) acc1[mt][nt][q] = 0.f;

    {
        const uint32_t aC = sb + SM_CB + (uint32_t)rowA * 128;
        const uint32_t aB = sb + SM_CB + 16384 + (uint32_t)rowB * 128;
        #pragma unroll
        for (int ks = 0; ks < 4; ks++) {
            uint32_t offA = (uint32_t)((((ks * 2 + cAq) ^ rA7) & 7) * 16);
            uint32_t offB = (uint32_t)((((ks * 2 + cBq) ^ rB7) & 7) * 16);
            uint32_t bh[4][2];
            #pragma unroll
            for (int ntp = 0; ntp < 2; ntp++) {
                uint32_t r0, r1, r2, r3;
                ldsm_x4(r0, r1, r2, r3, aB + ntp * 2048 + offB);
                bh[ntp*2][0]=r0; bh[ntp*2][1]=r1; bh[ntp*2+1][0]=r2; bh[ntp*2+1][1]=r3;
            }
            #pragma unroll
            for (int mt = 0; mt < 4; mt++) {
                uint32_t ah[4];
                ldsm_x4(ah[0], ah[1], ah[2], ah[3], aC + mt * 2048 + offA);
                #pragma unroll
                for (int nt = 0; nt < 4; nt++)
                    mma_fp16(acc1[mt][nt], ah, bh[nt]);
            }
        }
    }

    // ---- WB[n][s] = exp(L_last - L_s) * B[s][n] ----
    {
        const float Llast = Lsm[127];
        const uint32_t BH = sb + SM_CB + 16384;
        int n = t >> 2;
        int s0 = (t & 3) * 32;
        #pragma unroll
        for (int sp = 0; sp < 16; sp++) {
            int sA = s0 + sp * 2, sB2 = sA + 1;
            float2 fA = h2f2(*(uint32_t*)(smem + (a128(BH, sA, n >> 1) - sb)));
            float2 fB = h2f2(*(uint32_t*)(smem + (a128(BH, sB2, n >> 1) - sb)));
            float bA = (n & 1) ? fA.y : fA.x;
            float bB = (n & 1) ? fB.y : fB.x;
            float vA = bA * __expf(Llast - Lsm[sA]);
            float vB = bB * __expf(Llast - Lsm[sB2]);
            *(uint32_t*)(smem + (a256(sb + SM_WB, n, sA >> 1) - sb)) = packh2(vA, vB);
        }
    }
    __syncthreads();

    // ---- write G (overwrites C/B region): scale+mask, fp16 ----
    {
        const uint32_t GH = sb + SM_CB;
        #pragma unroll
        for (int mt = 0; mt < 4; mt++) {
            int l0 = wm * 64 + mt * 16 + lr;
            int l1 = l0 + 8;
            #pragma unroll
            for (int nt = 0; nt < 4; nt++) {
                int s0 = wn * 32 + nt * 8 + lc * 2;
                float Ll0 = Lsm[l0], Ll1 = Lsm[l1];
                float Ls0 = Lsm[s0], Ls1 = Lsm[s0 + 1];
                float e00 = (s0     <= l0) ? acc1[mt][nt][0] * __expf(Ll0 - Ls0) : 0.f;
                float e01 = (s0 + 1 <= l0) ? acc1[mt][nt][1] * __expf(Ll0 - Ls1) : 0.f;
                float e10 = (s0     <= l1) ? acc1[mt][nt][2] * __expf(Ll1 - Ls0) : 0.f;
                float e11 = (s0 + 1 <= l1) ? acc1[mt][nt][3] * __expf(Ll1 - Ls1) : 0.f;
                *(uint32_t*)(smem + (a256(GH, l0, s0 >> 1) - sb)) = packh2(e00, e01);
                *(uint32_t*)(smem + (a256(GH, l1, s0 >> 1) - sb)) = packh2(e10, e11);
            }
        }
    }
    __syncthreads();

    // ---- step 3: Y = G @ X   (M=128 l, N=128 p, K=128 s); X^T via trans-ldsm
    {
        float acc3[4][4][4];
        #pragma unroll
        for (int mt = 0; mt < 4; mt++)
            #pragma unroll
            for (int nt = 0; nt < 4; nt++)
                #pragma unroll
                for (int q = 0; q < 4; q++) acc3[mt][nt][q] = 0.f;

        const uint32_t aG = sb + SM_CB + (uint32_t)rowA * 256;
        // trans-ldsm lane mapping for B operand: s-row bit at lane>>3, p bit at lane>>4
        const int sOffB = ((lane >> 3) & 1) * 8 + (lane & 7);
        const int pOffB = ((lane >> 4) & 1) * 8;
        #pragma unroll
        for (int ks = 0; ks < 8; ks++) {
            int cqa = ks * 2 + cAq;
            uint32_t offA = (uint32_t)(((((cqa & 7) ^ rA7)) | (cqa & 8)) * 16);
            uint32_t bh[4][2];
            #pragma unroll
            for (int ntp = 0; ntp < 2; ntp++) {
                int prow = wn * 32 + ntp * 16 + pOffB;
                int srow = ks * 16 + sOffB;
                uint32_t r0, r1, r2, r3;
                ldsm_x4_t(r0, r1, r2, r3, a256(sb + SM_XT, srow, prow >> 1));
                bh[ntp*2][0]=r0; bh[ntp*2][1]=r1; bh[ntp*2+1][0]=r2; bh[ntp*2+1][1]=r3;
            }
            #pragma unroll
            for (int mt = 0; mt < 4; mt++) {
                uint32_t ah[4];
                ldsm_x4(ah[0], ah[1], ah[2], ah[3], aG + mt * 4096 + offA);
                #pragma unroll
                for (int nt = 0; nt < 4; nt++)
                    mma_fp16(acc3[mt][nt], ah, bh[nt]);
            }
        }
        const float Dh = Dvec[h];
        #pragma unroll
        for (int mt = 0; mt < 4; mt++) {
            int l0 = wm * 64 + mt * 16 + lr;
            int l1 = l0 + 8;
            #pragma unroll
            for (int nt = 0; nt < 4; nt++) {
                int p0 = wn * 32 + nt * 8 + lc * 2;
                float2 x0 = *(const float2*)(xbc + (base + l0) * CONV_DIM + xcol + p0);
                float2 x1 = *(const float2*)(xbc + (base + l1) * CONV_DIM + xcol + p0);
                *(float2*)(yout + (base + l0) * D_INNER + xcol + p0) =
                    make_float2(fmaf(Dh, x0.x, acc3[mt][nt][0]),
                                fmaf(Dh, x0.y, acc3[mt][nt][1]));
                *(float2*)(yout + (base + l1) * D_INNER + xcol + p0) =
                    make_float2(fmaf(Dh, x1.x, acc3[mt][nt][2]),
                                fmaf(Dh, x1.y, acc3[mt][nt][3]));
            }
        }
    }

    // ---- step 4: S_end[p][n] = X^T @ WB^T  (M=128 p, N=64 n, K=128 s) ----
    {
        const int wm4 = warp >> 1, wn4 = warp & 1;
        const int rowB4 = wn4 * 32 + ((lane >> 4) & 1) * 8 + (lane & 7);
        const int rB47 = rowB4 & 7;
        // trans-ldsm lane mapping for A operand: s bit at lane>>4, p bit at lane>>3
        const int sOffA = ((lane >> 4) & 1) * 8 + (lane & 7);
        const int pOffA = ((lane >> 3) & 1) * 8;

        float acc4[2][4][4];
        #pragma unroll
        for (int mt = 0; mt < 2; mt++)
            #pragma unroll
            for (int nt = 0; nt < 4; nt++)
                #pragma unroll
                for (int q = 0; q < 4; q++) acc4[mt][nt][q] = 0.f;

        const uint32_t aW = sb + SM_WB + (uint32_t)rowB4 * 256;
        #pragma unroll
        for (int ks = 0; ks < 8; ks++) {
            int cqb = ks * 2 + cBq;
            uint32_t offB = (uint32_t)(((((cqb & 7) ^ rB47)) | (cqb & 8)) * 16);
            uint32_t bh[4][2];
            #pragma unroll
            for (int ntp = 0; ntp < 2; ntp++) {
                uint32_t r0, r1, r2, r3;
                ldsm_x4(r0, r1, r2, r3, aW + ntp * 4096 + offB);
                bh[ntp*2][0]=r0; bh[ntp*2][1]=r1; bh[ntp*2+1][0]=r2; bh[ntp*2+1][1]=r3;
            }
            #pragma unroll
            for (int mt = 0; mt < 2; mt++) {
                int prow = wm4 * 32 + mt * 16 + pOffA;
                int srow = ks * 16 + sOffA;
                uint32_t ah[4];
                ldsm_x4_t(ah[0], ah[1], ah[2], ah[3],
                          a256(sb + SM_XT, srow, prow >> 1));
                #pragma unroll
                for (int nt = 0; nt < 4; nt++)
                    mma_fp16(acc4[mt][nt], ah, bh[nt]);
            }
        }
        float* stbase = states +
            ((size_t)(((b * NHEADS + h) * NCHUNK) + c) * HEADDIM) * D_STATE;
        #pragma unroll
        for (int mt = 0; mt < 2; mt++) {
            int p0 = wm4 * 32 + mt * 16 + lr;
            int p1 = p0 + 8;
            #pragma unroll
            for (int nt = 0; nt < 4; nt++) {
                int n0 = wn4 * 32 + nt * 8 + lc * 2;
                *(float2*)(stbase + (size_t)p0 * D_STATE + n0) =
                    make_float2(acc4[mt][nt][0], acc4[mt][nt][1]);
                *(float2*)(stbase + (size_t)p1 * D_STATE + n0) =
                    make_float2(acc4[mt][nt][2], acc4[mt][nt][3]);
            }
        }
    }
}

// ---------------- chunked scan: stage 2 (combine, p-sliced) ----------------
__global__ __launch_bounds__(256) void scan_combine_kernel(
    float* __restrict__ states, const float* __restrict__ cum)
{
    const int h   = blockIdx.x;
    const int b   = blockIdx.y;
    const int sl  = blockIdx.z;
    const int tid = threadIdx.x;

    __shared__ float dprod[NCHUNK];
    if (tid < NCHUNK)
        dprod[tid] = cum[(size_t)(((b * NHEADS + h) * NCHUNK) + tid) * LCHUNK + LCHUNK - 1];
    __syncthreads();

    const size_t chunk_stride = (size_t)HEADDIM * D_STATE;
    float* base = states + (size_t)((b * NHEADS + h) * NCHUNK) * chunk_stride
                         + (size_t)sl * 1024;

    float4 e = make_float4(0.f, 0.f, 0.f, 0.f);
    const int idx = tid;

    for (int c = 0; c < NCHUNK; c++) {
        float d = dprod[c];
        float4* p = (float4*)(base + c * chunk_stride);
        float4 s = p[idx];
        p[idx] = e;
        e.x = fmaf(e.x, d, s.x);
        e.y = fmaf(e.y, d, s.y);
        e.z = fmaf(e.z, d, s.z);
        e.w = fmaf(e.w, d, s.w);
    }
}

// ---------------- chunked scan: stage 3 (fp16 tensor-core GEMM) ------------
#define FX_A 0u
#define FX_B 16384u
#define FX_CUM 32768u
#define FX_SMEM 33280u

__global__ __launch_bounds__(256) void scan_fix_mm(
    const float* __restrict__ states, const float* __restrict__ cum,
    const __half* __restrict__ xbch, float* __restrict__ yout)
{
    extern __shared__ char smem[];
    const uint32_t sb = smem_to_u32(smem);
    const int c = blockIdx.x + 1;
    const int h = blockIdx.y;
    const int b = blockIdx.z;
    const int t = threadIdx.x;
    const int warp = t >> 5, lane = t & 31;
    const int lr = lane >> 2, lc = lane & 3;
    const int wm = warp >> 2, wn = warp & 3;

    const size_t base = (size_t)b * SEQLEN + (size_t)c * LCHUNK;
    const size_t cumbase = (size_t)(((b * NHEADS + h) * NCHUNK) + c) * LCHUNK;
    const int xcol = h * HEADDIM;
    float* cum_sm = (float*)(smem + FX_CUM);

    if (t < 128) cum_sm[t] = cum[cumbase + t];
    __syncthreads();

    const float* stbase = states +
        ((size_t)(((b * NHEADS + h) * NCHUNK) + c) * HEADDIM) * D_STATE;
    #pragma unroll
    for (int i = 0; i < 16; i++) {
        int idx = t + i * 256;
        int r = idx >> 5, col2 = idx & 31;
        float cm = cum_sm[r];
        float2 vC = h2f2(*(const uint32_t*)(xbch + (base + r) * CONV_DIM + D_INNER + 64 + col2 * 2));
        *(uint32_t*)(smem + (a128(sb + FX_A, r, col2) - sb)) =
            packh2(vC.x * cm, vC.y * cm);
        float2 vS = *(const float2*)(stbase + (size_t)r * D_STATE + col2 * 2);
        *(uint32_t*)(smem + (a128(sb + FX_B, r, col2) - sb)) = packh2(vS.x, vS.y);
    }
    __syncthreads();

    const int rowA = wm * 64 + ((lane >> 3) & 1) * 8 + (lane & 7);
    const int rowB = wn * 32 + ((lane >> 4) & 1) * 8 + (lane & 7);
    const int cAq = (lane >> 4) & 1;
    const int cBq = (lane >> 3) & 1;
    const int rA7 = rowA & 7, rB7 = rowB & 7;

    float acc[4][4][4];
    #pragma unroll
    for (int mt = 0; mt < 4; mt++)
        #pragma unroll
        for (int nt = 0; nt < 4; nt++)
            #pragma unroll
            for (int q = 0; q < 4; q++) acc[mt][nt][q] = 0.f;

    {
        const uint32_t aA = sb + FX_A + (uint32_t)rowA * 128;
        const uint32_t aB = sb + FX_B + (uint32_t)rowB * 128;
        #pragma unroll
        for (int ks = 0; ks < 4; ks++) {
            uint32_t offA = (uint32_t)((((ks * 2 + cAq) ^ rA7) & 7) * 16);
            uint32_t offB = (uint32_t)((((ks * 2 + cBq) ^ rB7) & 7) * 16);
            uint32_t bh[4][2];
            #pragma unroll
            for (int ntp = 0; ntp < 2; ntp++) {
                uint32_t r0, r1, r2, r3;
                ldsm_x4(r0, r1, r2, r3, aB + ntp * 2048 + offB);
                bh[ntp*2][0]=r0; bh[ntp*2][1]=r1; bh[ntp*2+1][0]=r2; bh[ntp*2+1][1]=r3;
            }
            #pragma unroll
            for (int mt = 0; mt < 4; mt++) {
                uint32_t ah[4];
                ldsm_x4(ah[0], ah[1], ah[2], ah[3], aA + mt * 2048 + offA);
                #pragma unroll
                for (int nt = 0; nt < 4; nt++)
                    mma_fp16(acc[mt][nt], ah, bh[nt]);
            }
        }
    }

    #pragma unroll
    for (int mt = 0; mt < 4; mt++) {
        int l0 = wm * 64 + mt * 16 + lr;
        int l1 = l0 + 8;
        #pragma unroll
        for (int nt = 0; nt < 4; nt++) {
            int p0 = wn * 32 + nt * 8 + lc * 2;
            float2* y0 = (float2*)(yout + (base + l0) * D_INNER + xcol + p0);
            float2* y1 = (float2*)(yout + (base + l1) * D_INNER + xcol + p0);
            float2 v0 = *y0, v1 = *y1;
            v0.x += acc[mt][nt][0]; v0.y += acc[mt][nt][1];
            v1.x += acc[mt][nt][2]; v1.y += acc[mt][nt][3];
            *y0 = v0; *y1 = v1;
        }
    }
}

// ---------------- RMSNorm + gate, fp16 output ------------------------------
__global__ __launch_bounds__(256) void rms_gate_kernel(
    const float* __restrict__ y, const float* __restrict__ zx,
    const float* __restrict__ rmsw, __half* __restrict__ yg)
{
    int r = blockIdx.x;
    const float*  yr = y  + (size_t)r * D_INNER;
    const float*  zr = zx + (size_t)r * D_IN_PROJ;
    const float4* y4 = (const float4*)yr;

    int tid = threadIdx.x;
    float ss = 0.f;
    #pragma unroll
    for (int i = 0; i < 2; i++) {
        float4 v = y4[tid + i * 256];
        ss += v.x*v.x + v.y*v.y + v.z*v.z + v.w*v.w;
    }
    #pragma unroll
    for (int o = 16; o > 0; o >>= 1) ss += __shfl_xor_sync(0xffffffffu, ss, o);
    __shared__ float red[8];
    if ((tid & 31) == 0) red[tid >> 5] = ss;
    __syncthreads();
    if (tid == 0) {
        float t = 0.f;
        #pragma unroll
        for (int i = 0; i < 8; i++) t += red[i];
        red[0] = rsqrtf(t * (1.f / D_INNER) + RMS_EPS);
    }
    __syncthreads();
    float rs = red[0];

    const float4* z4 = (const float4*)zr;
    const float4* w4 = (const float4*)rmsw;
    uint2* gh = (uint2*)(yg + (size_t)r * D_INNER);
    #pragma unroll
    for (int i = 0; i < 2; i++) {
        int c = tid + i * 256;
        float4 v = y4[c];
        float4 z = z4[c];
        float4 w = w4[c];
        float4 o;
        o.x = v.x * rs * w.x * fast_sigmoid(z.x);
        o.y = v.y * rs * w.y * fast_sigmoid(z.y);
        o.z = v.z * rs * w.z * fast_sigmoid(z.z);
        o.w = v.w * rs * w.w * fast_sigmoid(z.w);
        gh[c] = make_uint2(packh2(o.x, o.y), packh2(o.z, o.w));
    }
}

// ---------------- launcher -------------------------------------------------
extern "C" void kernel_launch(void* const* d_in, const int* in_sizes, int n_in,
                              void* d_out, int out_size)
{
    const float* u        = (const float*)d_in[0];
    const float* in_proj  = (const float*)d_in[1];
    const float* conv_w   = (const float*)d_in[2];
    const float* conv_b   = (const float*)d_in[3];
    const float* dt_bias  = (const float*)d_in[4];
    const float* A_log    = (const float*)d_in[5];
    const float* Dv       = (const float*)d_in[6];
    const float* rms_w    = (const float*)d_in[7];
    const float* out_w    = (const float*)d_in[8];
    float* out = (float*)d_out;

    float *zx, *xbc, *ldec, *y, *st, *cum;
    __half *xbch, *uh, *w1h, *w2h, *ygh;
    cudaGetSymbolAddress((void**)&zx,   g_zx);
    cudaGetSymbolAddress((void**)&xbc,  g_xbc);
    cudaGetSymbolAddress((void**)&xbch, g_xbch);
    cudaGetSymbolAddress((void**)&ldec, g_ldec);
    cudaGetSymbolAddress((void**)&y,    g_y);
    cudaGetSymbolAddress((void**)&st,   g_st);
    cudaGetSymbolAddress((void**)&cum,  g_cum);
    cudaGetSymbolAddress((void**)&uh,   g_uh);
    cudaGetSymbolAddress((void**)&w1h,  g_w1h);
    cudaGetSymbolAddress((void**)&w2h,  g_w2h);
    cudaGetSymbolAddress((void**)&ygh,  g_ygh);

    cudaFuncSetAttribute(gemm_fp16,
        cudaFuncAttributeMaxDynamicSharedMemorySize, GB_SMEM_BYTES);
    cudaFuncSetAttribute(scan_matmul_kernel,
        cudaFuncAttributeMaxDynamicSharedMemorySize, SM_SMEM);
    cudaFuncSetAttribute(scan_fix_mm,
        cudaFuncAttributeMaxDynamicSharedMemorySize, FX_SMEM);

    static cudaStream_t s1 = nullptr;
    static cudaEvent_t evFork = nullptr, evJoin = nullptr;
    if (!s1) {
        cudaStreamCreateWithFlags(&s1, cudaStreamNonBlocking);
        cudaEventCreateWithFlags(&evFork, cudaEventDisableTiming);
        cudaEventCreateWithFlags(&evJoin, cudaEventDisableTiming);
    }

    // 0) convert u, w1 to fp16
    {
        int n4u = NROWS * D_MODEL / 4;
        split_kernel<<<(n4u + 255) / 256, 256>>>(u, uh, n4u);
        int n4w1 = D_IN_PROJ * D_MODEL / 4;
        split_kernel<<<(n4w1 + 255) / 256, 256>>>(in_proj, w1h, n4w1);
    }
    // 1a) in_proj GEMM, xBC+dt columns
    {
        const int Nxbc = D_IN_PROJ - D_INNER;
        dim3 grid((Nxbc + GB_N - 1) / GB_N, NROWS / GB_M);
        gemm_fp16<<<grid, 256, GB_SMEM_BYTES>>>(
            uh, w1h + (size_t)D_INNER * D_MODEL,
            zx + D_INNER, NROWS, Nxbc, D_MODEL, D_IN_PROJ);
    }
    // fork: 1b) z columns + w2 convert on side stream
    cudaEventRecord(evFork, 0);
    cudaStreamWaitEvent(s1, evFork, 0);
    {
        dim3 grid(D_INNER / GB_N, NROWS / GB_M);
        gemm_fp16<<<grid, 256, GB_SMEM_BYTES, s1>>>(
            uh, w1h, zx, NROWS, D_INNER, D_MODEL, D_IN_PROJ);
        int n4w2 = D_MODEL * D_INNER / 4;
        split_kernel<<<(n4w2 + 255) / 256, 256, 0, s1>>>(out_w, w2h, n4w2);
    }
    cudaEventRecord(evJoin, s1);

    // 2) conv + silu (+ fp16 mirror)
    {
        dim3 grid((CONV_DIM + 255) / 256, SEQLEN / 256, BATCH);
        conv_kernel<<<grid, 256>>>(zx, conv_w, conv_b, xbc, xbch);
    }
    // 3) log-decay precompute
    decay_kernel<<<(NROWS * NHEADS + 255) / 256, 256>>>(zx, dt_bias, A_log, ldec);
    // 4) chunked SSM scan — all tensor-core
    {
        dim3 grid(NCHUNK, NHEADS, BATCH);
        scan_matmul_kernel<<<grid, 256, SM_SMEM>>>(xbc, xbch, ldec, Dv, y, st, cum);
    }
    {
        dim3 grid(NHEADS, BATCH, 8);
        scan_combine_kernel<<<grid, 256>>>(st, cum);
    }
    {
        dim3 grid(NCHUNK - 1, NHEADS, BATCH);
        scan_fix_mm<<<grid, 256, FX_SMEM>>>(st, cum, xbch, y);
    }
    cudaStreamWaitEvent(0, evJoin, 0);
    // 5) rmsnorm + gate
    rms_gate_kernel<<<NROWS, 256>>>(y, zx, rms_w, ygh);
    // 6) out_proj GEMM
    {
        dim3 grid(D_MODEL / GB_N, NROWS / GB_M);
        gemm_fp16<<<grid, 256, GB_SMEM_BYTES>>>(ygh, w2h, out,
                                                NROWS, D_MODEL, D_INNER, D_MODEL);
    }
}